// round 14
// baseline (speedup 1.0000x reference)
#include <cuda_runtime.h>
#include <cuda_fp16.h>
#include <math.h>
#include <stdint.h>

// Problem constants
#define B_   2
#define S_   2048
#define DM_  1024
#define H_   16
#define DH_  64
#define M_   (B_ * S_)          // 4096 rows
#define ROWSTRIDE 3072          // qkv row stride (3*DM_)

// Scratch (allocation-free rule: __device__ globals)
__device__ __half g_qkv16[(size_t)M_ * 3 * DM_];
__device__ __half g_x16[(size_t)M_ * DM_];
__device__ __half g_wq16[(size_t)3 * DM_ * DM_];
__device__ __half g_wo16[(size_t)DM_ * DM_];
__device__ __half g_attn16[(size_t)M_ * DM_];
__device__ float2 g_rope[(size_t)S_ * 16];      // (cos, sin) per (pos, pair)

// Correctly-rounded fp32 inv_freq table: 10000^(-p/16) = 10^(-p/4)
__constant__ float c_invf[16] = {
    1.0f,                    5.623413251903491e-01f,
    3.1622776601683794e-01f, 1.7782794100389228e-01f,
    1.0e-01f,                5.623413251903491e-02f,
    3.1622776601683794e-02f, 1.7782794100389228e-02f,
    1.0e-02f,                5.623413251903491e-03f,
    3.1622776601683794e-03f, 1.7782794100389228e-03f,
    1.0e-03f,                5.623413251903491e-04f,
    3.1622776601683794e-04f, 1.7782794100389228e-04f
};

// q pre-scale: (1/sqrt(64)) * log2(e)  -> scores land in log2 domain
#define QSCALE 0.18033688011112042f

// ---------------------------------------------------------------------------
// PTX helpers
// ---------------------------------------------------------------------------
__device__ __forceinline__ uint32_t smem_u32(const void* p) {
    uint32_t a;
    asm("{ .reg .u64 t; cvta.to.shared.u64 t, %1; cvt.u32.u64 %0, t; }"
        : "=r"(a) : "l"(p));
    return a;
}
__device__ __forceinline__ float exp2_(float x) {
    float y;
    asm("ex2.approx.f32 %0, %1;" : "=f"(y) : "f"(x));
    return y;
}

#define LDSM_X4(r0, r1, r2, r3, addr) \
    asm volatile("ldmatrix.sync.aligned.m8n8.x4.shared.b16 {%0,%1,%2,%3}, [%4];" \
                 : "=r"(r0), "=r"(r1), "=r"(r2), "=r"(r3) : "r"(addr))
#define LDSM_X4T(r0, r1, r2, r3, addr) \
    asm volatile("ldmatrix.sync.aligned.m8n8.x4.trans.shared.b16 {%0,%1,%2,%3}, [%4];" \
                 : "=r"(r0), "=r"(r1), "=r"(r2), "=r"(r3) : "r"(addr))

#define CP_ASYNC16(dst, src) \
    asm volatile("cp.async.cg.shared.global [%0], [%1], 16;" \
                 :: "r"(dst), "l"(src))
#define CP_COMMIT() asm volatile("cp.async.commit_group;" ::: "memory")
#define CP_WAIT(n)  asm volatile("cp.async.wait_group %0;" :: "n"(n) : "memory")

// fp16 mma
__device__ __forceinline__ void mma16816h(float* c, const uint32_t* a,
                                          const uint32_t* b) {
    asm volatile(
        "mma.sync.aligned.m16n8k16.row.col.f32.f16.f16.f32 "
        "{%0,%1,%2,%3}, {%4,%5,%6,%7}, {%8,%9}, {%0,%1,%2,%3};"
        : "+f"(c[0]), "+f"(c[1]), "+f"(c[2]), "+f"(c[3])
        : "r"(a[0]), "r"(a[1]), "r"(a[2]), "r"(a[3]), "r"(b[0]), "r"(b[1]));
}

__device__ __forceinline__ uint32_t packh(float a, float b) {
    __half2 t = __float22half2_rn(make_float2(a, b));
    return *(uint32_t*)&t;
}

// ---------------------------------------------------------------------------
// build RoPE table: g_rope[s*16 + p] = (cos, sin)(s * inv_freq[p])
// ---------------------------------------------------------------------------
__global__ __launch_bounds__(256) void build_rope(float2* __restrict__ t)
{
    int i = blockIdx.x * blockDim.x + threadIdx.x;   // 0 .. 32767
    int s = i >> 4, p = i & 15;
    float sn, cs;
    sincosf((float)s * c_invf[p], &sn, &cs);
    t[i] = make_float2(cs, sn);
}

// ---------------------------------------------------------------------------
// fused convert: all three fp32 tensors -> fp16 in one launch
// ---------------------------------------------------------------------------
__global__ __launch_bounds__(256) void convert_all(
    const float* __restrict__ s0, __half* __restrict__ d0, int n0,
    const float* __restrict__ s1, __half* __restrict__ d1, int n1,
    const float* __restrict__ s2, __half* __restrict__ d2, int n2)
{
    int i = blockIdx.x * blockDim.x + threadIdx.x;
    const float* src;
    __half* dst;
    if (i < n0) { src = s0; dst = d0; }
    else if (i < n0 + n1) { src = s1; dst = d1; i -= n0; }
    else if (i < n0 + n1 + n2) { src = s2; dst = d2; i -= n0 + n1; }
    else return;
    float4 v = ((const float4*)src)[i];
    __half2 h0 = __float22half2_rn(make_float2(v.x, v.y));
    __half2 h1 = __float22half2_rn(make_float2(v.z, v.w));
    uint2 hp;
    hp.x = *(uint32_t*)&h0; hp.y = *(uint32_t*)&h1;
    ((uint2*)dst)[i] = hp;
}

// ---------------------------------------------------------------------------
// RoPE on one bias-added pair via table; q scaled by QSCALE (log2 domain)
// ---------------------------------------------------------------------------
__device__ __forceinline__ float2 rope_pair(float2 v, int row, int col,
                                            const float2* __restrict__ rt) {
    int hd = col & 63;
    int sec = col >> 10;                 // 0=q 1=k 2=v
    if (sec < 2 && hd < 32) {
        float2 t = rt[((row & (S_ - 1)) << 4) | (hd >> 1)];
        float x1 = v.x, x2 = v.y;
        v.x = x1 * t.x - x2 * t.y;
        v.y = x2 * t.x + x1 * t.y;
    }
    if (sec == 0) { v.x *= QSCALE; v.y *= QSCALE; }
    return v;
}

// ---------------------------------------------------------------------------
// HMMA GEMM, single-pass fp16, 512 threads (16 warps, warp tile 32x32),
// cp.async 5-buffer pipeline with prefetch distance 3, ONE barrier/iter.
// C[M,N] = A[M,K] @ W[N,K]^T + bias.
// ---------------------------------------------------------------------------
#define BK 32
#define ASTR 40
#define STG_H (128 * ASTR)                     // halfs per operand tile
#define NSTAGE 5
#define GEMM_SMEM_BYTES (NSTAGE * 2 * STG_H * 2)   // 102400

__global__ __launch_bounds__(512, 2) void gemm_mma_h16(
    const __half* __restrict__ A, const __half* __restrict__ Bm,
    const float* __restrict__ bias, float* __restrict__ C,
    __half* __restrict__ C16, const float2* __restrict__ rt,
    int M, int N, int K)
{
    extern __shared__ __half gsm[];
    const uint32_t uG = smem_u32(gsm);

    const int tid = threadIdx.x;
    const int wid = tid >> 5;
    const int lane = tid & 31;
    const int warp_m = wid & 3;          // 4 warps in M (32 rows each)
    const int warp_n = wid >> 2;         // 4 warps in N (32 cols each)
    const int bm = blockIdx.y * 128;
    const int bn = blockIdx.x * 128;
    const int q8 = lane >> 3;
    const int l7 = lane & 7;

    const __half* srcA = A + (size_t)bm * K;
    const __half* srcB = Bm + (size_t)bn * K;

    float acc[2][4][4];
#pragma unroll
    for (int i = 0; i < 2; i++)
#pragma unroll
        for (int j = 0; j < 4; j++)
#pragma unroll
            for (int e = 0; e < 4; e++) acc[i][j][e] = 0.f;

    const int niter = K / BK;

    auto issue_stage = [&](int itx, int buf) {
        const int k0 = itx * BK;
        const uint32_t sbase = (uint32_t)(buf * 2 * STG_H) * 2;
        int r = tid >> 2, c8 = (tid & 3) * 8;
        size_t g = (size_t)r * K + k0 + c8;
        uint32_t dA = uG + sbase + (uint32_t)(r * ASTR + c8) * 2;
        uint32_t dB = uG + sbase + (uint32_t)(STG_H + r * ASTR + c8) * 2;
        CP_ASYNC16(dA, srcA + g);
        CP_ASYNC16(dB, srcB + g);
        CP_COMMIT();
    };

    issue_stage(0, 0);
    issue_stage(1, 1);
    issue_stage(2, 2);

    for (int it = 0; it < niter; it++) {
        const int buf = it % NSTAGE;
        if (it + 3 < niter) {
            issue_stage(it + 3, (it + 3) % NSTAGE);
            CP_WAIT(3);
        } else if (it + 2 < niter) {
            CP_WAIT(2);
        } else if (it + 1 < niter) {
            CP_WAIT(1);
        } else {
            CP_WAIT(0);
        }
        __syncthreads();

        const uint32_t uA = uG + (uint32_t)(buf * 2 * STG_H) * 2;
        const uint32_t uB = uA + STG_H * 2;

#pragma unroll
        for (int ks = 0; ks < 2; ks++) {
            uint32_t af[2][4];
#pragma unroll
            for (int mi = 0; mi < 2; mi++) {
                uint32_t r = (uint32_t)((warp_m * 32 + mi * 16 + (lane & 15)) * ASTR
                                        + ks * 16 + (lane >> 4) * 8) * 2;
                LDSM_X4(af[mi][0], af[mi][1], af[mi][2], af[mi][3], uA + r);
            }
#pragma unroll
            for (int ni2 = 0; ni2 < 2; ni2++) {
                uint32_t r = (uint32_t)(
                    (warp_n * 32 + ni2 * 16 + (q8 >> 1) * 8 + l7) * ASTR
                    + ks * 16 + (q8 & 1) * 8) * 2;
                uint32_t b4[4];
                LDSM_X4(b4[0], b4[1], b4[2], b4[3], uB + r);
#pragma unroll
                for (int mi = 0; mi < 2; mi++) {
                    mma16816h(acc[mi][ni2 * 2], af[mi], b4);
                    mma16816h(acc[mi][ni2 * 2 + 1], af[mi], b4 + 2);
                }
            }
        }
    }

    const int m0 = bm + warp_m * 32;
    const int n0 = bn + warp_n * 32;
#pragma unroll
    for (int mi = 0; mi < 2; mi++) {
#pragma unroll
        for (int ni = 0; ni < 4; ni++) {
            int col = n0 + ni * 8 + (lane & 3) * 2;
            float2 bv = *(const float2*)(bias + col);
            int r0 = m0 + mi * 16 + (lane >> 2);
            float2 o0, o1;
            o0.x = acc[mi][ni][0] + bv.x;
            o0.y = acc[mi][ni][1] + bv.y;
            o1.x = acc[mi][ni][2] + bv.x;
            o1.y = acc[mi][ni][3] + bv.y;
            if (C16) {
                o0 = rope_pair(o0, r0, col, rt);
                o1 = rope_pair(o1, r0 + 8, col, rt);
                *(__half2*)(C16 + (size_t)r0 * N + col) = __float22half2_rn(o0);
                *(__half2*)(C16 + (size_t)(r0 + 8) * N + col) = __float22half2_rn(o1);
            } else {
                *(float2*)(C + (size_t)r0 * N + col) = o0;
                *(float2*)(C + (size_t)(r0 + 8) * N + col) = o1;
            }
        }
    }
}

// ---------------------------------------------------------------------------
// Flash attention, fp16 HMMA, log2-domain softmax. Q register-resident.
// K/V: 4-buffer cp.async pipeline, prefetch distance 2, one barrier/iter.
// Row-sum reduction DEFERRED to epilogue (lane-local partials in the loop).
// ---------------------------------------------------------------------------
#define FST 72
#define KVT (64 * FST)                          // halfs per K or V tile
#define FNSTG 4
#define FLASH_SMEM_BYTES (FNSTG * 2 * KVT * 2)  // 73728

__global__ __launch_bounds__(256, 2) void flash_h16(
    const __half* __restrict__ qkv16, __half* __restrict__ attn16)
{
    extern __shared__ __half hsm[];
    const uint32_t uF = smem_u32(hsm);

    const int tid = threadIdx.x;
    const int wid = tid >> 5, lane = tid & 31;
    const int bhid = blockIdx.y;
    const int bb = bhid >> 4, h = bhid & 15;
    const int q0 = blockIdx.x * 128;

    const size_t rowbase = (size_t)bb * S_ * ROWSTRIDE;
    const __half* qb = qkv16 + rowbase + h * DH_;
    const __half* kb = qb + DM_;
    const __half* vb = qb + 2 * DM_;

    // Stage Q into smem, lift fragments to registers
#pragma unroll
    for (int it = 0; it < 4; it++) {
        int L = it * 256 + tid;
        int r = L >> 3, c8 = (L & 7) * 8;
        size_t g = (size_t)(q0 + r) * ROWSTRIDE + c8;
        *(uint4*)(hsm + r * FST + c8) = *(const uint4*)(qb + g);
    }
    __syncthreads();

    uint32_t qf[4][4];
#pragma unroll
    for (int kc = 0; kc < 4; kc++) {
        uint32_t qa = (uint32_t)((wid * 16 + (lane & 15)) * FST + kc * 16
                                 + 8 * (lane >> 4)) * 2;
        LDSM_X4(qf[kc][0], qf[kc][1], qf[kc][2], qf[kc][3], uF + qa);
    }
    __syncthreads();

    float o[8][4];
#pragma unroll
    for (int ni = 0; ni < 8; ni++)
#pragma unroll
        for (int e = 0; e < 4; e++) o[ni][e] = 0.f;
    float m0 = -INFINITY, m1 = -INFINITY;
    float l0 = 0.f, l1 = 0.f;            // lane-local partial sums (deferred)

    const int q8 = lane >> 3;
    const int l7 = lane & 7;

    auto issue_kv = [&](int tt, int buf) {
        const uint32_t sbase = (uint32_t)(buf * 2 * KVT) * 2;
#pragma unroll
        for (int it = 0; it < 4; it++) {
            int L = it * 256 + tid;
            int tsel = L >> 9;
            int r = (L >> 3) & 63, c8 = (L & 7) * 8;
            const __half* srcp = (tsel == 0 ? kb : vb)
                                 + (size_t)(tt * 64 + r) * ROWSTRIDE + c8;
            uint32_t d = uF + sbase + (uint32_t)(tsel * KVT + r * FST + c8) * 2;
            CP_ASYNC16(d, srcp);
        }
        CP_COMMIT();
    };

    issue_kv(0, 0);
    issue_kv(1, 1);

    const int ntile = S_ / 64;
    for (int t = 0; t < ntile; t++) {
        const int buf = t & 3;
        if (t + 2 < ntile) {
            issue_kv(t + 2, (t + 2) & 3);
            CP_WAIT(2);
        } else if (t + 1 < ntile) {
            CP_WAIT(1);
        } else {
            CP_WAIT(0);
        }
        __syncthreads();

        const uint32_t uK = uF + (uint32_t)(buf * 2 * KVT) * 2;
        const uint32_t uV = uK + (uint32_t)KVT * 2;

        // S = Q @ K^T over 64 keys (scores already in log2 domain)
        float s[8][4];
#pragma unroll
        for (int ni = 0; ni < 8; ni++)
#pragma unroll
            for (int e = 0; e < 4; e++) s[ni][e] = 0.f;

#pragma unroll
        for (int kc = 0; kc < 4; kc++) {
#pragma unroll
            for (int ni2 = 0; ni2 < 4; ni2++) {
                uint32_t ka = (uint32_t)(
                    (ni2 * 16 + (q8 >> 1) * 8 + l7) * FST
                    + kc * 16 + (q8 & 1) * 8) * 2;
                uint32_t k4[4];
                LDSM_X4(k4[0], k4[1], k4[2], k4[3], uK + ka);
                mma16816h(s[ni2 * 2], qf[kc], k4);
                mma16816h(s[ni2 * 2 + 1], qf[kc], k4 + 2);
            }
        }

        // Online softmax (log2 domain); row max still needs the quad shfl
        float rm0 = -INFINITY, rm1 = -INFINITY;
#pragma unroll
        for (int ni = 0; ni < 8; ni++) {
            rm0 = fmaxf(rm0, fmaxf(s[ni][0], s[ni][1]));
            rm1 = fmaxf(rm1, fmaxf(s[ni][2], s[ni][3]));
        }
        rm0 = fmaxf(rm0, __shfl_xor_sync(0xffffffffu, rm0, 1));
        rm0 = fmaxf(rm0, __shfl_xor_sync(0xffffffffu, rm0, 2));
        rm1 = fmaxf(rm1, __shfl_xor_sync(0xffffffffu, rm1, 1));
        rm1 = fmaxf(rm1, __shfl_xor_sync(0xffffffffu, rm1, 2));

        float mn0 = fmaxf(m0, rm0), mn1 = fmaxf(m1, rm1);
        float c0 = exp2_(m0 - mn0), c1 = exp2_(m1 - mn1);
        m0 = mn0; m1 = mn1;

        // lane-local partial row sums; quad reduction deferred to epilogue
        float rs0 = 0.f, rs1 = 0.f;
        uint32_t ph[8][2];
#pragma unroll
        for (int ni = 0; ni < 8; ni++) {
            s[ni][0] = exp2_(s[ni][0] - mn0);
            s[ni][1] = exp2_(s[ni][1] - mn0);
            s[ni][2] = exp2_(s[ni][2] - mn1);
            s[ni][3] = exp2_(s[ni][3] - mn1);
            rs0 += s[ni][0] + s[ni][1];
            rs1 += s[ni][2] + s[ni][3];
            ph[ni][0] = packh(s[ni][0], s[ni][1]);
            ph[ni][1] = packh(s[ni][2], s[ni][3]);
        }
        l0 = l0 * c0 + rs0;              // c0/c1 are quad-uniform
        l1 = l1 * c1 + rs1;

#pragma unroll
        for (int ni = 0; ni < 8; ni++) {
            o[ni][0] *= c0; o[ni][1] *= c0;
            o[ni][2] *= c1; o[ni][3] *= c1;
        }

        // O += P @ V over 64 keys
#pragma unroll
        for (int kc2 = 0; kc2 < 4; kc2++) {
            uint32_t af[4] = {ph[2 * kc2][0], ph[2 * kc2][1],
                              ph[2 * kc2 + 1][0], ph[2 * kc2 + 1][1]};
#pragma unroll
            for (int ni2 = 0; ni2 < 4; ni2++) {
                uint32_t va = (uint32_t)(
                    (kc2 * 16 + (q8 & 1) * 8 + l7) * FST
                    + ni2 * 16 + (q8 >> 1) * 8) * 2;
                uint32_t v4[4];
                LDSM_X4T(v4[0], v4[1], v4[2], v4[3], uV + va);
                mma16816h(o[ni2 * 2], af, v4);
                mma16816h(o[ni2 * 2 + 1], af, v4 + 2);
            }
        }
    }

    // Epilogue: single deferred quad reduction of l, normalize, store fp16
    l0 += __shfl_xor_sync(0xffffffffu, l0, 1);
    l0 += __shfl_xor_sync(0xffffffffu, l0, 2);
    l1 += __shfl_xor_sync(0xffffffffu, l1, 1);
    l1 += __shfl_xor_sync(0xffffffffu, l1, 2);
    float inv0 = 1.f / l0, inv1 = 1.f / l1;
    int r0 = q0 + wid * 16 + (lane >> 2);
    size_t obase = ((size_t)bb * S_ + r0) * DM_ + h * DH_;
#pragma unroll
    for (int ni = 0; ni < 8; ni++) {
        int col = ni * 8 + (lane & 3) * 2;
        *(__half2*)(attn16 + obase + col) =
            __float22half2_rn(make_float2(o[ni][0] * inv0, o[ni][1] * inv0));
        *(__half2*)(attn16 + obase + 8 * DM_ + col) =
            __float22half2_rn(make_float2(o[ni][2] * inv1, o[ni][3] * inv1));
    }
}

// ---------------------------------------------------------------------------
extern "C" void kernel_launch(void* const* d_in, const int* in_sizes, int n_in,
                              void* d_out, int out_size)
{
    const float* x    = (const float*)d_in[0];
    const float* Wqkv = (const float*)d_in[1];
    const float* bqkv = (const float*)d_in[2];
    const float* Wout = (const float*)d_in[3];
    const float* bout = (const float*)d_in[4];
    float* out = (float*)d_out;

    __half *qkv16, *x16, *wq16, *wo16, *attn16;
    float2* ropeT;
    cudaGetSymbolAddress((void**)&qkv16, g_qkv16);
    cudaGetSymbolAddress((void**)&x16, g_x16);
    cudaGetSymbolAddress((void**)&wq16, g_wq16);
    cudaGetSymbolAddress((void**)&wo16, g_wo16);
    cudaGetSymbolAddress((void**)&attn16, g_attn16);
    cudaGetSymbolAddress((void**)&ropeT, g_rope);

    cudaFuncSetAttribute(gemm_mma_h16,
                         cudaFuncAttributeMaxDynamicSharedMemorySize,
                         GEMM_SMEM_BYTES);
    cudaFuncSetAttribute(flash_h16, cudaFuncAttributeMaxDynamicSharedMemorySize,
                         FLASH_SMEM_BYTES);

    // 0a) build RoPE cos/sin table (32768 entries)
    build_rope<<<(S_ * 16) / 256, 256>>>(ropeT);

    // 0b) convert inputs to fp16 (single fused launch)
    const int n0 = M_ * DM_ / 4, n1 = 3 * DM_ * DM_ / 4, n2 = DM_ * DM_ / 4;
    convert_all<<<(n0 + n1 + n2 + 255) / 256, 256>>>(x, x16, n0,
                                                     Wqkv, wq16, n1,
                                                     Wout, wo16, n2);

    // 1) QKV projection + fused bias + table-RoPE(+log2e q-scale) + fp16
    dim3 g1(3 * DM_ / 128, M_ / 128);
    gemm_mma_h16<<<g1, 512, GEMM_SMEM_BYTES>>>(x16, wq16, bqkv,
                                               nullptr, qkv16, ropeT,
                                               M_, 3 * DM_, DM_);

    // 2) Flash attention (fp16, log2-domain softmax, deferred l-reduction)
    dim3 g3(S_ / 128, B_ * H_);
    flash_h16<<<g3, 256, FLASH_SMEM_BYTES>>>(qkv16, attn16);

    // 3) Out projection (fp16), fp32 output + bias
    dim3 g4(DM_ / 128, M_ / 128);
    gemm_mma_h16<<<g4, 512, GEMM_SMEM_BYTES>>>(attn16, wo16, bout,
                                               out, nullptr, nullptr,
                                               M_, DM_, DM_);
}

// round 15
// speedup vs baseline: 1.0391x; 1.0391x over previous
#include <cuda_runtime.h>
#include <cuda_fp16.h>
#include <math.h>
#include <stdint.h>

// Problem constants
#define B_   2
#define S_   2048
#define DM_  1024
#define H_   16
#define DH_  64
#define M_   (B_ * S_)          // 4096 rows
#define ROWSTRIDE 3072          // qkv row stride (3*DM_)

// Scratch (allocation-free rule: __device__ globals)
__device__ __half g_qkv16[(size_t)M_ * 3 * DM_];
__device__ __half g_x16[(size_t)M_ * DM_];
__device__ __half g_wq16[(size_t)3 * DM_ * DM_];
__device__ __half g_wo16[(size_t)DM_ * DM_];
__device__ __half g_attn16[(size_t)M_ * DM_];

// Correctly-rounded fp32 inv_freq table: 10000^(-p/16) = 10^(-p/4)
__constant__ float c_invf[16] = {
    1.0f,                    5.623413251903491e-01f,
    3.1622776601683794e-01f, 1.7782794100389228e-01f,
    1.0e-01f,                5.623413251903491e-02f,
    3.1622776601683794e-02f, 1.7782794100389228e-02f,
    1.0e-02f,                5.623413251903491e-03f,
    3.1622776601683794e-03f, 1.7782794100389228e-03f,
    1.0e-03f,                5.623413251903491e-04f,
    3.1622776601683794e-04f, 1.7782794100389228e-04f
};

// q pre-scale: (1/sqrt(64)) * log2(e)  -> scores land in log2 domain
#define QSCALE 0.18033688011112042f

// ---------------------------------------------------------------------------
// PTX helpers
// ---------------------------------------------------------------------------
__device__ __forceinline__ uint32_t smem_u32(const void* p) {
    uint32_t a;
    asm("{ .reg .u64 t; cvta.to.shared.u64 t, %1; cvt.u32.u64 %0, t; }"
        : "=r"(a) : "l"(p));
    return a;
}
__device__ __forceinline__ float exp2_(float x) {
    float y;
    asm("ex2.approx.f32 %0, %1;" : "=f"(y) : "f"(x));
    return y;
}

#define LDSM_X4(r0, r1, r2, r3, addr) \
    asm volatile("ldmatrix.sync.aligned.m8n8.x4.shared.b16 {%0,%1,%2,%3}, [%4];" \
                 : "=r"(r0), "=r"(r1), "=r"(r2), "=r"(r3) : "r"(addr))
#define LDSM_X4T(r0, r1, r2, r3, addr) \
    asm volatile("ldmatrix.sync.aligned.m8n8.x4.trans.shared.b16 {%0,%1,%2,%3}, [%4];" \
                 : "=r"(r0), "=r"(r1), "=r"(r2), "=r"(r3) : "r"(addr))

#define CP_ASYNC16(dst, src) \
    asm volatile("cp.async.cg.shared.global [%0], [%1], 16;" \
                 :: "r"(dst), "l"(src))
#define CP_COMMIT() asm volatile("cp.async.commit_group;" ::: "memory")
#define CP_WAIT(n)  asm volatile("cp.async.wait_group %0;" :: "n"(n) : "memory")

// fp16 mma
__device__ __forceinline__ void mma16816h(float* c, const uint32_t* a,
                                          const uint32_t* b) {
    asm volatile(
        "mma.sync.aligned.m16n8k16.row.col.f32.f16.f16.f32 "
        "{%0,%1,%2,%3}, {%4,%5,%6,%7}, {%8,%9}, {%0,%1,%2,%3};"
        : "+f"(c[0]), "+f"(c[1]), "+f"(c[2]), "+f"(c[3])
        : "r"(a[0]), "r"(a[1]), "r"(a[2]), "r"(a[3]), "r"(b[0]), "r"(b[1]));
}

__device__ __forceinline__ uint32_t packh(float a, float b) {
    __half2 t = __float22half2_rn(make_float2(a, b));
    return *(uint32_t*)&t;
}

// ---------------------------------------------------------------------------
// fused convert: all three fp32 tensors -> fp16 in one launch
// ---------------------------------------------------------------------------
__global__ __launch_bounds__(256) void convert_all(
    const float* __restrict__ s0, __half* __restrict__ d0, int n0,
    const float* __restrict__ s1, __half* __restrict__ d1, int n1,
    const float* __restrict__ s2, __half* __restrict__ d2, int n2)
{
    int i = blockIdx.x * blockDim.x + threadIdx.x;
    const float* src;
    __half* dst;
    if (i < n0) { src = s0; dst = d0; }
    else if (i < n0 + n1) { src = s1; dst = d1; i -= n0; }
    else if (i < n0 + n1 + n2) { src = s2; dst = d2; i -= n0 + n1; }
    else return;
    float4 v = ((const float4*)src)[i];
    __half2 h0 = __float22half2_rn(make_float2(v.x, v.y));
    __half2 h1 = __float22half2_rn(make_float2(v.z, v.w));
    uint2 hp;
    hp.x = *(uint32_t*)&h0; hp.y = *(uint32_t*)&h1;
    ((uint2*)dst)[i] = hp;
}

// ---------------------------------------------------------------------------
// RoPE on one bias-added pair; q additionally scaled by QSCALE (log2 domain)
// ---------------------------------------------------------------------------
__device__ __forceinline__ float2 rope_pair(float2 v, int row, int col) {
    int hd = col & 63;
    int sec = col >> 10;                 // 0=q 1=k 2=v
    if (sec < 2 && hd < 32) {
        float inv_freq = c_invf[hd >> 1];
        float sn, cs;
        sincosf((float)(row & (S_ - 1)) * inv_freq, &sn, &cs);
        float x1 = v.x, x2 = v.y;
        v.x = x1 * cs - x2 * sn;
        v.y = x2 * cs + x1 * sn;
    }
    if (sec == 0) { v.x *= QSCALE; v.y *= QSCALE; }
    return v;
}

// ---------------------------------------------------------------------------
// HMMA GEMM, single-pass fp16, 512 threads (16 warps, warp tile 32x32),
// cp.async 5-buffer pipeline with prefetch distance 3, ONE barrier/iter.
// C[M,N] = A[M,K] @ W[N,K]^T + bias.  (round-13 structure, unchanged)
// ---------------------------------------------------------------------------
#define BK 32
#define ASTR 40
#define STG_H (128 * ASTR)                     // halfs per operand tile
#define NSTAGE 5
#define GEMM_SMEM_BYTES (NSTAGE * 2 * STG_H * 2)   // 102400

__global__ __launch_bounds__(512, 2) void gemm_mma_h16(
    const __half* __restrict__ A, const __half* __restrict__ Bm,
    const float* __restrict__ bias, float* __restrict__ C,
    __half* __restrict__ C16, int M, int N, int K)
{
    extern __shared__ __half gsm[];
    const uint32_t uG = smem_u32(gsm);

    const int tid = threadIdx.x;
    const int wid = tid >> 5;
    const int lane = tid & 31;
    const int warp_m = wid & 3;          // 4 warps in M (32 rows each)
    const int warp_n = wid >> 2;         // 4 warps in N (32 cols each)
    const int bm = blockIdx.y * 128;
    const int bn = blockIdx.x * 128;
    const int q8 = lane >> 3;
    const int l7 = lane & 7;

    const __half* srcA = A + (size_t)bm * K;
    const __half* srcB = Bm + (size_t)bn * K;

    float acc[2][4][4];
#pragma unroll
    for (int i = 0; i < 2; i++)
#pragma unroll
        for (int j = 0; j < 4; j++)
#pragma unroll
            for (int e = 0; e < 4; e++) acc[i][j][e] = 0.f;

    const int niter = K / BK;

    auto issue_stage = [&](int itx, int buf) {
        const int k0 = itx * BK;
        const uint32_t sbase = (uint32_t)(buf * 2 * STG_H) * 2;
        int r = tid >> 2, c8 = (tid & 3) * 8;
        size_t g = (size_t)r * K + k0 + c8;
        uint32_t dA = uG + sbase + (uint32_t)(r * ASTR + c8) * 2;
        uint32_t dB = uG + sbase + (uint32_t)(STG_H + r * ASTR + c8) * 2;
        CP_ASYNC16(dA, srcA + g);
        CP_ASYNC16(dB, srcB + g);
        CP_COMMIT();
    };

    issue_stage(0, 0);
    issue_stage(1, 1);
    issue_stage(2, 2);

    for (int it = 0; it < niter; it++) {
        const int buf = it % NSTAGE;
        if (it + 3 < niter) {
            issue_stage(it + 3, (it + 3) % NSTAGE);
            CP_WAIT(3);
        } else if (it + 2 < niter) {
            CP_WAIT(2);
        } else if (it + 1 < niter) {
            CP_WAIT(1);
        } else {
            CP_WAIT(0);
        }
        __syncthreads();

        const uint32_t uA = uG + (uint32_t)(buf * 2 * STG_H) * 2;
        const uint32_t uB = uA + STG_H * 2;

#pragma unroll
        for (int ks = 0; ks < 2; ks++) {
            uint32_t af[2][4];
#pragma unroll
            for (int mi = 0; mi < 2; mi++) {
                uint32_t r = (uint32_t)((warp_m * 32 + mi * 16 + (lane & 15)) * ASTR
                                        + ks * 16 + (lane >> 4) * 8) * 2;
                LDSM_X4(af[mi][0], af[mi][1], af[mi][2], af[mi][3], uA + r);
            }
#pragma unroll
            for (int ni2 = 0; ni2 < 2; ni2++) {
                uint32_t r = (uint32_t)(
                    (warp_n * 32 + ni2 * 16 + (q8 >> 1) * 8 + l7) * ASTR
                    + ks * 16 + (q8 & 1) * 8) * 2;
                uint32_t b4[4];
                LDSM_X4(b4[0], b4[1], b4[2], b4[3], uB + r);
#pragma unroll
                for (int mi = 0; mi < 2; mi++) {
                    mma16816h(acc[mi][ni2 * 2], af[mi], b4);
                    mma16816h(acc[mi][ni2 * 2 + 1], af[mi], b4 + 2);
                }
            }
        }
    }

    const int m0 = bm + warp_m * 32;
    const int n0 = bn + warp_n * 32;
#pragma unroll
    for (int mi = 0; mi < 2; mi++) {
#pragma unroll
        for (int ni = 0; ni < 4; ni++) {
            int col = n0 + ni * 8 + (lane & 3) * 2;
            float2 bv = *(const float2*)(bias + col);
            int r0 = m0 + mi * 16 + (lane >> 2);
            float2 o0, o1;
            o0.x = acc[mi][ni][0] + bv.x;
            o0.y = acc[mi][ni][1] + bv.y;
            o1.x = acc[mi][ni][2] + bv.x;
            o1.y = acc[mi][ni][3] + bv.y;
            if (C16) {
                o0 = rope_pair(o0, r0, col);
                o1 = rope_pair(o1, r0 + 8, col);
                *(__half2*)(C16 + (size_t)r0 * N + col) = __float22half2_rn(o0);
                *(__half2*)(C16 + (size_t)(r0 + 8) * N + col) = __float22half2_rn(o1);
            } else {
                *(float2*)(C + (size_t)r0 * N + col) = o0;
                *(float2*)(C + (size_t)(r0 + 8) * N + col) = o1;
            }
        }
    }
}

// ---------------------------------------------------------------------------
// Flash attention, fp16 HMMA, log2-domain softmax. Q register-resident.
// K/V: 4-buffer cp.async pipeline, prefetch distance 2, one barrier/iter.
// Deltas vs round 13: deferred l-reduction + warp-uniform rescale skip
// (skip is bit-identical: skipped iff c0 == c1 == 1.0 for all lanes).
// ---------------------------------------------------------------------------
#define FST 72
#define KVT (64 * FST)                          // halfs per K or V tile
#define FNSTG 4
#define FLASH_SMEM_BYTES (FNSTG * 2 * KVT * 2)  // 73728

__global__ __launch_bounds__(256, 2) void flash_h16(
    const __half* __restrict__ qkv16, __half* __restrict__ attn16)
{
    extern __shared__ __half hsm[];
    const uint32_t uF = smem_u32(hsm);

    const int tid = threadIdx.x;
    const int wid = tid >> 5, lane = tid & 31;
    const int bhid = blockIdx.y;
    const int bb = bhid >> 4, h = bhid & 15;
    const int q0 = blockIdx.x * 128;

    const size_t rowbase = (size_t)bb * S_ * ROWSTRIDE;
    const __half* qb = qkv16 + rowbase + h * DH_;
    const __half* kb = qb + DM_;
    const __half* vb = qb + 2 * DM_;

    // Stage Q into smem, lift fragments to registers
#pragma unroll
    for (int it = 0; it < 4; it++) {
        int L = it * 256 + tid;
        int r = L >> 3, c8 = (L & 7) * 8;
        size_t g = (size_t)(q0 + r) * ROWSTRIDE + c8;
        *(uint4*)(hsm + r * FST + c8) = *(const uint4*)(qb + g);
    }
    __syncthreads();

    uint32_t qf[4][4];
#pragma unroll
    for (int kc = 0; kc < 4; kc++) {
        uint32_t qa = (uint32_t)((wid * 16 + (lane & 15)) * FST + kc * 16
                                 + 8 * (lane >> 4)) * 2;
        LDSM_X4(qf[kc][0], qf[kc][1], qf[kc][2], qf[kc][3], uF + qa);
    }
    __syncthreads();

    float o[8][4];
#pragma unroll
    for (int ni = 0; ni < 8; ni++)
#pragma unroll
        for (int e = 0; e < 4; e++) o[ni][e] = 0.f;
    float m0 = -INFINITY, m1 = -INFINITY;
    float l0 = 0.f, l1 = 0.f;            // lane-local partials (deferred)

    const int q8 = lane >> 3;
    const int l7 = lane & 7;

    auto issue_kv = [&](int tt, int buf) {
        const uint32_t sbase = (uint32_t)(buf * 2 * KVT) * 2;
#pragma unroll
        for (int it = 0; it < 4; it++) {
            int L = it * 256 + tid;
            int tsel = L >> 9;
            int r = (L >> 3) & 63, c8 = (L & 7) * 8;
            const __half* srcp = (tsel == 0 ? kb : vb)
                                 + (size_t)(tt * 64 + r) * ROWSTRIDE + c8;
            uint32_t d = uF + sbase + (uint32_t)(tsel * KVT + r * FST + c8) * 2;
            CP_ASYNC16(d, srcp);
        }
        CP_COMMIT();
    };

    issue_kv(0, 0);
    issue_kv(1, 1);

    const int ntile = S_ / 64;
    for (int t = 0; t < ntile; t++) {
        const int buf = t & 3;
        if (t + 2 < ntile) {
            issue_kv(t + 2, (t + 2) & 3);
            CP_WAIT(2);
        } else if (t + 1 < ntile) {
            CP_WAIT(1);
        } else {
            CP_WAIT(0);
        }
        __syncthreads();

        const uint32_t uK = uF + (uint32_t)(buf * 2 * KVT) * 2;
        const uint32_t uV = uK + (uint32_t)KVT * 2;

        // S = Q @ K^T over 64 keys (scores already in log2 domain)
        float s[8][4];
#pragma unroll
        for (int ni = 0; ni < 8; ni++)
#pragma unroll
            for (int e = 0; e < 4; e++) s[ni][e] = 0.f;

#pragma unroll
        for (int kc = 0; kc < 4; kc++) {
#pragma unroll
            for (int ni2 = 0; ni2 < 4; ni2++) {
                uint32_t ka = (uint32_t)(
                    (ni2 * 16 + (q8 >> 1) * 8 + l7) * FST
                    + kc * 16 + (q8 & 1) * 8) * 2;
                uint32_t k4[4];
                LDSM_X4(k4[0], k4[1], k4[2], k4[3], uK + ka);
                mma16816h(s[ni2 * 2], qf[kc], k4);
                mma16816h(s[ni2 * 2 + 1], qf[kc], k4 + 2);
            }
        }

        // Online softmax (log2 domain)
        float rm0 = -INFINITY, rm1 = -INFINITY;
#pragma unroll
        for (int ni = 0; ni < 8; ni++) {
            rm0 = fmaxf(rm0, fmaxf(s[ni][0], s[ni][1]));
            rm1 = fmaxf(rm1, fmaxf(s[ni][2], s[ni][3]));
        }
        rm0 = fmaxf(rm0, __shfl_xor_sync(0xffffffffu, rm0, 1));
        rm0 = fmaxf(rm0, __shfl_xor_sync(0xffffffffu, rm0, 2));
        rm1 = fmaxf(rm1, __shfl_xor_sync(0xffffffffu, rm1, 1));
        rm1 = fmaxf(rm1, __shfl_xor_sync(0xffffffffu, rm1, 2));

        float mn0 = fmaxf(m0, rm0), mn1 = fmaxf(m1, rm1);
        // Warp-uniform rescale skip: if no lane's max changed, c0=c1=1.0
        // exactly and the rescale is an identity -> bit-identical skip.
        bool changed = (mn0 > m0) || (mn1 > m1);
        if (__any_sync(0xffffffffu, changed)) {
            float c0 = exp2_(m0 - mn0), c1 = exp2_(m1 - mn1);
            l0 *= c0; l1 *= c1;
#pragma unroll
            for (int ni = 0; ni < 8; ni++) {
                o[ni][0] *= c0; o[ni][1] *= c0;
                o[ni][2] *= c1; o[ni][3] *= c1;
            }
            m0 = mn0; m1 = mn1;
        }

        // lane-local partial row sums; quad reduction deferred to epilogue
        uint32_t ph[8][2];
#pragma unroll
        for (int ni = 0; ni < 8; ni++) {
            s[ni][0] = exp2_(s[ni][0] - m0);
            s[ni][1] = exp2_(s[ni][1] - m0);
            s[ni][2] = exp2_(s[ni][2] - m1);
            s[ni][3] = exp2_(s[ni][3] - m1);
            l0 += s[ni][0] + s[ni][1];
            l1 += s[ni][2] + s[ni][3];
            ph[ni][0] = packh(s[ni][0], s[ni][1]);
            ph[ni][1] = packh(s[ni][2], s[ni][3]);
        }

        // O += P @ V over 64 keys
#pragma unroll
        for (int kc2 = 0; kc2 < 4; kc2++) {
            uint32_t af[4] = {ph[2 * kc2][0], ph[2 * kc2][1],
                              ph[2 * kc2 + 1][0], ph[2 * kc2 + 1][1]};
#pragma unroll
            for (int ni2 = 0; ni2 < 4; ni2++) {
                uint32_t va = (uint32_t)(
                    (kc2 * 16 + (q8 & 1) * 8 + l7) * FST
                    + ni2 * 16 + (q8 >> 1) * 8) * 2;
                uint32_t v4[4];
                LDSM_X4T(v4[0], v4[1], v4[2], v4[3], uV + va);
                mma16816h(o[ni2 * 2], af, v4);
                mma16816h(o[ni2 * 2 + 1], af, v4 + 2);
            }
        }
    }

    // Epilogue: deferred quad reduction of l, normalize, store fp16
    l0 += __shfl_xor_sync(0xffffffffu, l0, 1);
    l0 += __shfl_xor_sync(0xffffffffu, l0, 2);
    l1 += __shfl_xor_sync(0xffffffffu, l1, 1);
    l1 += __shfl_xor_sync(0xffffffffu, l1, 2);
    float inv0 = 1.f / l0, inv1 = 1.f / l1;
    int r0 = q0 + wid * 16 + (lane >> 2);
    size_t obase = ((size_t)bb * S_ + r0) * DM_ + h * DH_;
#pragma unroll
    for (int ni = 0; ni < 8; ni++) {
        int col = ni * 8 + (lane & 3) * 2;
        *(__half2*)(attn16 + obase + col) =
            __float22half2_rn(make_float2(o[ni][0] * inv0, o[ni][1] * inv0));
        *(__half2*)(attn16 + obase + 8 * DM_ + col) =
            __float22half2_rn(make_float2(o[ni][2] * inv1, o[ni][3] * inv1));
    }
}

// ---------------------------------------------------------------------------
extern "C" void kernel_launch(void* const* d_in, const int* in_sizes, int n_in,
                              void* d_out, int out_size)
{
    const float* x    = (const float*)d_in[0];
    const float* Wqkv = (const float*)d_in[1];
    const float* bqkv = (const float*)d_in[2];
    const float* Wout = (const float*)d_in[3];
    const float* bout = (const float*)d_in[4];
    float* out = (float*)d_out;

    __half *qkv16, *x16, *wq16, *wo16, *attn16;
    cudaGetSymbolAddress((void**)&qkv16, g_qkv16);
    cudaGetSymbolAddress((void**)&x16, g_x16);
    cudaGetSymbolAddress((void**)&wq16, g_wq16);
    cudaGetSymbolAddress((void**)&wo16, g_wo16);
    cudaGetSymbolAddress((void**)&attn16, g_attn16);

    cudaFuncSetAttribute(gemm_mma_h16,
                         cudaFuncAttributeMaxDynamicSharedMemorySize,
                         GEMM_SMEM_BYTES);
    cudaFuncSetAttribute(flash_h16, cudaFuncAttributeMaxDynamicSharedMemorySize,
                         FLASH_SMEM_BYTES);

    // 0) convert inputs to fp16 (single fused launch)
    const int n0 = M_ * DM_ / 4, n1 = 3 * DM_ * DM_ / 4, n2 = DM_ * DM_ / 4;
    convert_all<<<(n0 + n1 + n2 + 255) / 256, 256>>>(x, x16, n0,
                                                     Wqkv, wq16, n1,
                                                     Wout, wo16, n2);

    // 1) QKV projection + fused bias + RoPE(+log2e q-scale) + fp16 convert
    dim3 g1(3 * DM_ / 128, M_ / 128);
    gemm_mma_h16<<<g1, 512, GEMM_SMEM_BYTES>>>(x16, wq16, bqkv,
                                               nullptr, qkv16,
                                               M_, 3 * DM_, DM_);

    // 2) Flash attention (fp16, log2-domain softmax)
    dim3 g3(S_ / 128, B_ * H_);
    flash_h16<<<g3, 256, FLASH_SMEM_BYTES>>>(qkv16, attn16);

    // 3) Out projection (fp16), fp32 output + bias
    dim3 g4(DM_ / 128, M_ / 128);
    gemm_mma_h16<<<g4, 512, GEMM_SMEM_BYTES>>>(attn16, wo16, bout,
                                               out, nullptr,
                                               M_, DM_, DM_);
}

// round 16
// speedup vs baseline: 1.0872x; 1.0464x over previous
#include <cuda_runtime.h>
#include <cuda_fp16.h>
#include <math.h>
#include <stdint.h>

// Problem constants
#define B_   2
#define S_   2048
#define DM_  1024
#define H_   16
#define DH_  64
#define M_   (B_ * S_)          // 4096 rows
#define ROWSTRIDE 3072          // qkv row stride (3*DM_)

// Scratch (allocation-free rule: __device__ globals)
__device__ __half g_qkv16[(size_t)M_ * 3 * DM_];
__device__ __half g_x16[(size_t)M_ * DM_];
__device__ __half g_wq16[(size_t)3 * DM_ * DM_];
__device__ __half g_wo16[(size_t)DM_ * DM_];
__device__ __half g_attn16[(size_t)M_ * DM_];

// Correctly-rounded fp32 inv_freq table: 10000^(-p/16) = 10^(-p/4)
__constant__ float c_invf[16] = {
    1.0f,                    5.623413251903491e-01f,
    3.1622776601683794e-01f, 1.7782794100389228e-01f,
    1.0e-01f,                5.623413251903491e-02f,
    3.1622776601683794e-02f, 1.7782794100389228e-02f,
    1.0e-02f,                5.623413251903491e-03f,
    3.1622776601683794e-03f, 1.7782794100389228e-03f,
    1.0e-03f,                5.623413251903491e-04f,
    3.1622776601683794e-04f, 1.7782794100389228e-04f
};

// q pre-scale: (1/sqrt(64)) * log2(e)  -> scores land in log2 domain
#define QSCALE 0.18033688011112042f

// ---------------------------------------------------------------------------
// PTX helpers
// ---------------------------------------------------------------------------
__device__ __forceinline__ uint32_t smem_u32(const void* p) {
    uint32_t a;
    asm("{ .reg .u64 t; cvta.to.shared.u64 t, %1; cvt.u32.u64 %0, t; }"
        : "=r"(a) : "l"(p));
    return a;
}
__device__ __forceinline__ float exp2_(float x) {
    float y;
    asm("ex2.approx.f32 %0, %1;" : "=f"(y) : "f"(x));
    return y;
}

#define LDSM_X4(r0, r1, r2, r3, addr) \
    asm volatile("ldmatrix.sync.aligned.m8n8.x4.shared.b16 {%0,%1,%2,%3}, [%4];" \
                 : "=r"(r0), "=r"(r1), "=r"(r2), "=r"(r3) : "r"(addr))
#define LDSM_X4T(r0, r1, r2, r3, addr) \
    asm volatile("ldmatrix.sync.aligned.m8n8.x4.trans.shared.b16 {%0,%1,%2,%3}, [%4];" \
                 : "=r"(r0), "=r"(r1), "=r"(r2), "=r"(r3) : "r"(addr))

#define CP_ASYNC16(dst, src) \
    asm volatile("cp.async.cg.shared.global [%0], [%1], 16;" \
                 :: "r"(dst), "l"(src))
#define CP_COMMIT() asm volatile("cp.async.commit_group;" ::: "memory")
#define CP_WAIT(n)  asm volatile("cp.async.wait_group %0;" :: "n"(n) : "memory")

// fp16 mma
__device__ __forceinline__ void mma16816h(float* c, const uint32_t* a,
                                          const uint32_t* b) {
    asm volatile(
        "mma.sync.aligned.m16n8k16.row.col.f32.f16.f16.f32 "
        "{%0,%1,%2,%3}, {%4,%5,%6,%7}, {%8,%9}, {%0,%1,%2,%3};"
        : "+f"(c[0]), "+f"(c[1]), "+f"(c[2]), "+f"(c[3])
        : "r"(a[0]), "r"(a[1]), "r"(a[2]), "r"(a[3]), "r"(b[0]), "r"(b[1]));
}

__device__ __forceinline__ uint32_t packh(float a, float b) {
    __half2 t = __float22half2_rn(make_float2(a, b));
    return *(uint32_t*)&t;
}

// ---------------------------------------------------------------------------
// fused convert: all three fp32 tensors -> fp16 in one launch
// ---------------------------------------------------------------------------
__global__ __launch_bounds__(256) void convert_all(
    const float* __restrict__ s0, __half* __restrict__ d0, int n0,
    const float* __restrict__ s1, __half* __restrict__ d1, int n1,
    const float* __restrict__ s2, __half* __restrict__ d2, int n2)
{
    int i = blockIdx.x * blockDim.x + threadIdx.x;
    const float* src;
    __half* dst;
    if (i < n0) { src = s0; dst = d0; }
    else if (i < n0 + n1) { src = s1; dst = d1; i -= n0; }
    else if (i < n0 + n1 + n2) { src = s2; dst = d2; i -= n0 + n1; }
    else return;
    float4 v = ((const float4*)src)[i];
    __half2 h0 = __float22half2_rn(make_float2(v.x, v.y));
    __half2 h1 = __float22half2_rn(make_float2(v.z, v.w));
    uint2 hp;
    hp.x = *(uint32_t*)&h0; hp.y = *(uint32_t*)&h1;
    ((uint2*)dst)[i] = hp;
}

// ---------------------------------------------------------------------------
// RoPE on one bias-added pair; q additionally scaled by QSCALE (log2 domain)
// ---------------------------------------------------------------------------
__device__ __forceinline__ float2 rope_pair(float2 v, int row, int col) {
    int hd = col & 63;
    int sec = col >> 10;                 // 0=q 1=k 2=v
    if (sec < 2 && hd < 32) {
        float inv_freq = c_invf[hd >> 1];
        float sn, cs;
        sincosf((float)(row & (S_ - 1)) * inv_freq, &sn, &cs);
        float x1 = v.x, x2 = v.y;
        v.x = x1 * cs - x2 * sn;
        v.y = x2 * cs + x1 * sn;
    }
    if (sec == 0) { v.x *= QSCALE; v.y *= QSCALE; }
    return v;
}

// ---------------------------------------------------------------------------
// HMMA GEMM, single-pass fp16, 512 threads (16 warps, warp tile 32x32),
// BK=64 (HALVED iteration count), cp.async 3-buffer pipeline, distance 1,
// ONE barrier/iter. C[M,N] = A[M,K] @ W[N,K]^T + bias.
// ---------------------------------------------------------------------------
#define BK 64
#define GST 72                                  // smem stride in halfs (64+8)
#define STG_H (128 * GST)                       // halfs per operand tile
#define NSTAGE 3
#define GEMM_SMEM_BYTES (NSTAGE * 2 * STG_H * 2)   // 110592

__global__ __launch_bounds__(512, 2) void gemm_mma_h16(
    const __half* __restrict__ A, const __half* __restrict__ Bm,
    const float* __restrict__ bias, float* __restrict__ C,
    __half* __restrict__ C16, int M, int N, int K)
{
    extern __shared__ __half gsm[];
    const uint32_t uG = smem_u32(gsm);

    const int tid = threadIdx.x;
    const int wid = tid >> 5;
    const int lane = tid & 31;
    const int warp_m = wid & 3;          // 4 warps in M (32 rows each)
    const int warp_n = wid >> 2;         // 4 warps in N (32 cols each)
    const int bm = blockIdx.y * 128;
    const int bn = blockIdx.x * 128;
    const int q8 = lane >> 3;
    const int l7 = lane & 7;

    const __half* srcA = A + (size_t)bm * K;
    const __half* srcB = Bm + (size_t)bn * K;

    float acc[2][4][4];
#pragma unroll
    for (int i = 0; i < 2; i++)
#pragma unroll
        for (int j = 0; j < 4; j++)
#pragma unroll
            for (int e = 0; e < 4; e++) acc[i][j][e] = 0.f;

    const int niter = K / BK;            // 16

    auto issue_stage = [&](int itx, int buf) {
        const int k0 = itx * BK;
        const uint32_t sbase = (uint32_t)(buf * 2 * STG_H) * 2;
        // tile = 128 rows x 64 halfs = 1024 uint4 slots; 2 per thread per tile
#pragma unroll
        for (int s = 0; s < 2; s++) {
            int slot = s * 512 + tid;
            int r = slot >> 3, c8 = (slot & 7) * 8;
            size_t g = (size_t)r * K + k0 + c8;
            uint32_t dA = uG + sbase + (uint32_t)(r * GST + c8) * 2;
            uint32_t dB = uG + sbase + (uint32_t)(STG_H + r * GST + c8) * 2;
            CP_ASYNC16(dA, srcA + g);
            CP_ASYNC16(dB, srcB + g);
        }
        CP_COMMIT();
    };

    issue_stage(0, 0);

    for (int it = 0; it < niter; it++) {
        const int buf = it % NSTAGE;
        // distance-1 issue-before-wait: writer (it+1)%3 vs readers it%3 and
        // stragglers on (it-1)%3 — all distinct mod 3. ONE barrier/iter.
        if (it + 1 < niter) {
            issue_stage(it + 1, (it + 1) % NSTAGE);
            CP_WAIT(1);
        } else {
            CP_WAIT(0);
        }
        __syncthreads();

        const uint32_t uA = uG + (uint32_t)(buf * 2 * STG_H) * 2;
        const uint32_t uB = uA + STG_H * 2;

#pragma unroll
        for (int ks = 0; ks < 4; ks++) {
            uint32_t af[2][4];
#pragma unroll
            for (int mi = 0; mi < 2; mi++) {
                uint32_t r = (uint32_t)((warp_m * 32 + mi * 16 + (lane & 15)) * GST
                                        + ks * 16 + (lane >> 4) * 8) * 2;
                LDSM_X4(af[mi][0], af[mi][1], af[mi][2], af[mi][3], uA + r);
            }
#pragma unroll
            for (int ni2 = 0; ni2 < 2; ni2++) {
                uint32_t r = (uint32_t)(
                    (warp_n * 32 + ni2 * 16 + (q8 >> 1) * 8 + l7) * GST
                    + ks * 16 + (q8 & 1) * 8) * 2;
                uint32_t b4[4];
                LDSM_X4(b4[0], b4[1], b4[2], b4[3], uB + r);
#pragma unroll
                for (int mi = 0; mi < 2; mi++) {
                    mma16816h(acc[mi][ni2 * 2], af[mi], b4);
                    mma16816h(acc[mi][ni2 * 2 + 1], af[mi], b4 + 2);
                }
            }
        }
    }

    const int m0 = bm + warp_m * 32;
    const int n0 = bn + warp_n * 32;
#pragma unroll
    for (int mi = 0; mi < 2; mi++) {
#pragma unroll
        for (int ni = 0; ni < 4; ni++) {
            int col = n0 + ni * 8 + (lane & 3) * 2;
            float2 bv = *(const float2*)(bias + col);
            int r0 = m0 + mi * 16 + (lane >> 2);
            float2 o0, o1;
            o0.x = acc[mi][ni][0] + bv.x;
            o0.y = acc[mi][ni][1] + bv.y;
            o1.x = acc[mi][ni][2] + bv.x;
            o1.y = acc[mi][ni][3] + bv.y;
            if (C16) {
                o0 = rope_pair(o0, r0, col);
                o1 = rope_pair(o1, r0 + 8, col);
                *(__half2*)(C16 + (size_t)r0 * N + col) = __float22half2_rn(o0);
                *(__half2*)(C16 + (size_t)(r0 + 8) * N + col) = __float22half2_rn(o1);
            } else {
                *(float2*)(C + (size_t)r0 * N + col) = o0;
                *(float2*)(C + (size_t)(r0 + 8) * N + col) = o1;
            }
        }
    }
}

// ---------------------------------------------------------------------------
// Flash attention (round-15 structure, unchanged), fp16 HMMA, log2 softmax.
// Q register-resident; K/V 4-buffer cp.async, distance 2, one barrier/iter.
// Deferred l-reduction + bit-identical warp-uniform rescale skip.
// ---------------------------------------------------------------------------
#define FST 72
#define KVT (64 * FST)                          // halfs per K or V tile
#define FNSTG 4
#define FLASH_SMEM_BYTES (FNSTG * 2 * KVT * 2)  // 73728

__global__ __launch_bounds__(256, 2) void flash_h16(
    const __half* __restrict__ qkv16, __half* __restrict__ attn16)
{
    extern __shared__ __half hsm[];
    const uint32_t uF = smem_u32(hsm);

    const int tid = threadIdx.x;
    const int wid = tid >> 5, lane = tid & 31;
    const int bhid = blockIdx.y;
    const int bb = bhid >> 4, h = bhid & 15;
    const int q0 = blockIdx.x * 128;

    const size_t rowbase = (size_t)bb * S_ * ROWSTRIDE;
    const __half* qb = qkv16 + rowbase + h * DH_;
    const __half* kb = qb + DM_;
    const __half* vb = qb + 2 * DM_;

    // Stage Q into smem, lift fragments to registers
#pragma unroll
    for (int it = 0; it < 4; it++) {
        int L = it * 256 + tid;
        int r = L >> 3, c8 = (L & 7) * 8;
        size_t g = (size_t)(q0 + r) * ROWSTRIDE + c8;
        *(uint4*)(hsm + r * FST + c8) = *(const uint4*)(qb + g);
    }
    __syncthreads();

    uint32_t qf[4][4];
#pragma unroll
    for (int kc = 0; kc < 4; kc++) {
        uint32_t qa = (uint32_t)((wid * 16 + (lane & 15)) * FST + kc * 16
                                 + 8 * (lane >> 4)) * 2;
        LDSM_X4(qf[kc][0], qf[kc][1], qf[kc][2], qf[kc][3], uF + qa);
    }
    __syncthreads();

    float o[8][4];
#pragma unroll
    for (int ni = 0; ni < 8; ni++)
#pragma unroll
        for (int e = 0; e < 4; e++) o[ni][e] = 0.f;
    float m0 = -INFINITY, m1 = -INFINITY;
    float l0 = 0.f, l1 = 0.f;            // lane-local partials (deferred)

    const int q8 = lane >> 3;
    const int l7 = lane & 7;

    auto issue_kv = [&](int tt, int buf) {
        const uint32_t sbase = (uint32_t)(buf * 2 * KVT) * 2;
#pragma unroll
        for (int it = 0; it < 4; it++) {
            int L = it * 256 + tid;
            int tsel = L >> 9;
            int r = (L >> 3) & 63, c8 = (L & 7) * 8;
            const __half* srcp = (tsel == 0 ? kb : vb)
                                 + (size_t)(tt * 64 + r) * ROWSTRIDE + c8;
            uint32_t d = uF + sbase + (uint32_t)(tsel * KVT + r * FST + c8) * 2;
            CP_ASYNC16(d, srcp);
        }
        CP_COMMIT();
    };

    issue_kv(0, 0);
    issue_kv(1, 1);

    const int ntile = S_ / 64;
    for (int t = 0; t < ntile; t++) {
        const int buf = t & 3;
        if (t + 2 < ntile) {
            issue_kv(t + 2, (t + 2) & 3);
            CP_WAIT(2);
        } else if (t + 1 < ntile) {
            CP_WAIT(1);
        } else {
            CP_WAIT(0);
        }
        __syncthreads();

        const uint32_t uK = uF + (uint32_t)(buf * 2 * KVT) * 2;
        const uint32_t uV = uK + (uint32_t)KVT * 2;

        // S = Q @ K^T over 64 keys (scores already in log2 domain)
        float s[8][4];
#pragma unroll
        for (int ni = 0; ni < 8; ni++)
#pragma unroll
            for (int e = 0; e < 4; e++) s[ni][e] = 0.f;

#pragma unroll
        for (int kc = 0; kc < 4; kc++) {
#pragma unroll
            for (int ni2 = 0; ni2 < 4; ni2++) {
                uint32_t ka = (uint32_t)(
                    (ni2 * 16 + (q8 >> 1) * 8 + l7) * FST
                    + kc * 16 + (q8 & 1) * 8) * 2;
                uint32_t k4[4];
                LDSM_X4(k4[0], k4[1], k4[2], k4[3], uK + ka);
                mma16816h(s[ni2 * 2], qf[kc], k4);
                mma16816h(s[ni2 * 2 + 1], qf[kc], k4 + 2);
            }
        }

        // Online softmax (log2 domain)
        float rm0 = -INFINITY, rm1 = -INFINITY;
#pragma unroll
        for (int ni = 0; ni < 8; ni++) {
            rm0 = fmaxf(rm0, fmaxf(s[ni][0], s[ni][1]));
            rm1 = fmaxf(rm1, fmaxf(s[ni][2], s[ni][3]));
        }
        rm0 = fmaxf(rm0, __shfl_xor_sync(0xffffffffu, rm0, 1));
        rm0 = fmaxf(rm0, __shfl_xor_sync(0xffffffffu, rm0, 2));
        rm1 = fmaxf(rm1, __shfl_xor_sync(0xffffffffu, rm1, 1));
        rm1 = fmaxf(rm1, __shfl_xor_sync(0xffffffffu, rm1, 2));

        float mn0 = fmaxf(m0, rm0), mn1 = fmaxf(m1, rm1);
        bool changed = (mn0 > m0) || (mn1 > m1);
        if (__any_sync(0xffffffffu, changed)) {
            float c0 = exp2_(m0 - mn0), c1 = exp2_(m1 - mn1);
            l0 *= c0; l1 *= c1;
#pragma unroll
            for (int ni = 0; ni < 8; ni++) {
                o[ni][0] *= c0; o[ni][1] *= c0;
                o[ni][2] *= c1; o[ni][3] *= c1;
            }
            m0 = mn0; m1 = mn1;
        }

        // lane-local partial row sums; quad reduction deferred to epilogue
        uint32_t ph[8][2];
#pragma unroll
        for (int ni = 0; ni < 8; ni++) {
            s[ni][0] = exp2_(s[ni][0] - m0);
            s[ni][1] = exp2_(s[ni][1] - m0);
            s[ni][2] = exp2_(s[ni][2] - m1);
            s[ni][3] = exp2_(s[ni][3] - m1);
            l0 += s[ni][0] + s[ni][1];
            l1 += s[ni][2] + s[ni][3];
            ph[ni][0] = packh(s[ni][0], s[ni][1]);
            ph[ni][1] = packh(s[ni][2], s[ni][3]);
        }

        // O += P @ V over 64 keys
#pragma unroll
        for (int kc2 = 0; kc2 < 4; kc2++) {
            uint32_t af[4] = {ph[2 * kc2][0], ph[2 * kc2][1],
                              ph[2 * kc2 + 1][0], ph[2 * kc2 + 1][1]};
#pragma unroll
            for (int ni2 = 0; ni2 < 4; ni2++) {
                uint32_t va = (uint32_t)(
                    (kc2 * 16 + (q8 & 1) * 8 + l7) * FST
                    + ni2 * 16 + (q8 >> 1) * 8) * 2;
                uint32_t v4[4];
                LDSM_X4T(v4[0], v4[1], v4[2], v4[3], uV + va);
                mma16816h(o[ni2 * 2], af, v4);
                mma16816h(o[ni2 * 2 + 1], af, v4 + 2);
            }
        }
    }

    // Epilogue: deferred quad reduction of l, normalize, store fp16
    l0 += __shfl_xor_sync(0xffffffffu, l0, 1);
    l0 += __shfl_xor_sync(0xffffffffu, l0, 2);
    l1 += __shfl_xor_sync(0xffffffffu, l1, 1);
    l1 += __shfl_xor_sync(0xffffffffu, l1, 2);
    float inv0 = 1.f / l0, inv1 = 1.f / l1;
    int r0 = q0 + wid * 16 + (lane >> 2);
    size_t obase = ((size_t)bb * S_ + r0) * DM_ + h * DH_;
#pragma unroll
    for (int ni = 0; ni < 8; ni++) {
        int col = ni * 8 + (lane & 3) * 2;
        *(__half2*)(attn16 + obase + col) =
            __float22half2_rn(make_float2(o[ni][0] * inv0, o[ni][1] * inv0));
        *(__half2*)(attn16 + obase + 8 * DM_ + col) =
            __float22half2_rn(make_float2(o[ni][2] * inv1, o[ni][3] * inv1));
    }
}

// ---------------------------------------------------------------------------
extern "C" void kernel_launch(void* const* d_in, const int* in_sizes, int n_in,
                              void* d_out, int out_size)
{
    const float* x    = (const float*)d_in[0];
    const float* Wqkv = (const float*)d_in[1];
    const float* bqkv = (const float*)d_in[2];
    const float* Wout = (const float*)d_in[3];
    const float* bout = (const float*)d_in[4];
    float* out = (float*)d_out;

    __half *qkv16, *x16, *wq16, *wo16, *attn16;
    cudaGetSymbolAddress((void**)&qkv16, g_qkv16);
    cudaGetSymbolAddress((void**)&x16, g_x16);
    cudaGetSymbolAddress((void**)&wq16, g_wq16);
    cudaGetSymbolAddress((void**)&wo16, g_wo16);
    cudaGetSymbolAddress((void**)&attn16, g_attn16);

    cudaFuncSetAttribute(gemm_mma_h16,
                         cudaFuncAttributeMaxDynamicSharedMemorySize,
                         GEMM_SMEM_BYTES);
    cudaFuncSetAttribute(flash_h16, cudaFuncAttributeMaxDynamicSharedMemorySize,
                         FLASH_SMEM_BYTES);

    // 0) convert inputs to fp16 (single fused launch)
    const int n0 = M_ * DM_ / 4, n1 = 3 * DM_ * DM_ / 4, n2 = DM_ * DM_ / 4;
    convert_all<<<(n0 + n1 + n2 + 255) / 256, 256>>>(x, x16, n0,
                                                     Wqkv, wq16, n1,
                                                     Wout, wo16, n2);

    // 1) QKV projection + fused bias + RoPE(+log2e q-scale) + fp16 convert
    dim3 g1(3 * DM_ / 128, M_ / 128);
    gemm_mma_h16<<<g1, 512, GEMM_SMEM_BYTES>>>(x16, wq16, bqkv,
                                               nullptr, qkv16,
                                               M_, 3 * DM_, DM_);

    // 2) Flash attention (fp16, log2-domain softmax)
    dim3 g3(S_ / 128, B_ * H_);
    flash_h16<<<g3, 256, FLASH_SMEM_BYTES>>>(qkv16, attn16);

    // 3) Out projection (fp16), fp32 output + bias
    dim3 g4(DM_ / 128, M_ / 128);
    gemm_mma_h16<<<g4, 512, GEMM_SMEM_BYTES>>>(attn16, wo16, bout,
                                               out, nullptr,
                                               M_, DM_, DM_);
}